// round 4
// baseline (speedup 1.0000x reference)
#include <cuda_runtime.h>
#include <math.h>

// Shapes
#define NROWS 4096
#define XLD   1184   // padded 1182 -> 1184 (news[1024] | price[158] | 2 zeros)
#define OFF_PRED 0
#define OFF_RW1  (NROWS)
#define OFF_HID  (NROWS + NROWS*64)
#define OFF_TK   (NROWS + 2*NROWS*64)
#define OFF_RW2  (NROWS + 2*NROWS*64 + NROWS*2)

// Scratch: X = [news_agg(1024) | price_agg(158) | pad2], row-major, 4096 x 1184
__device__ float g_X[(size_t)NROWS * XLD];

// ---------------------------------------------------------------------------
// Kernel 1: masked news aggregation + price mean -> g_X   (memory-bound)
// ---------------------------------------------------------------------------
__global__ __launch_bounds__(256) void k_agg(const float* __restrict__ price,
                                             const float* __restrict__ news,
                                             const float* __restrict__ mask)
{
    int n   = blockIdx.x;
    int tid = threadIdx.x;
    const float* nf   = news  + (size_t)n * 32 * 1024 + tid * 4;
    const float* pf   = price + (size_t)n * 32 * 158;
    const float* mrow = mask  + n * 32;

    float4 acc = make_float4(0.f, 0.f, 0.f, 0.f);
    float msum = 0.f, pacc = 0.f;

#pragma unroll 4
    for (int t = 0; t < 32; ++t) {
        float m = __ldg(mrow + t);
        msum += m;
        float4 v = *(const float4*)(nf + t * 1024);
        acc.x = fmaf(m, v.x, acc.x);
        acc.y = fmaf(m, v.y, acc.y);
        acc.z = fmaf(m, v.z, acc.z);
        acc.w = fmaf(m, v.w, acc.w);
        if (tid < 158) pacc += __ldg(pf + t * 158 + tid);
    }

    float inv = 1.f / fmaxf(msum, 1e-6f);
    float* xr = g_X + (size_t)n * XLD;
    *(float4*)(xr + tid * 4) =
        make_float4(acc.x * inv, acc.y * inv, acc.z * inv, acc.w * inv);
    if (tid < 158)       xr[1024 + tid] = pacc * (1.f / 32.f);
    else if (tid < 160)  xr[1024 + tid] = 0.f;   // zero pad cols 1182,1183
}

// ---------------------------------------------------------------------------
// Kernel 2: fused router GEMM + gate GEMM + top2 routing + sparse expert path
// 128 blocks x 256 threads, each block owns 32 n-rows.
// ---------------------------------------------------------------------------
__global__ __launch_bounds__(256) void k_main(
    const float* __restrict__ rW,  const float* __restrict__ rb,
    const float* __restrict__ gW,  const float* __restrict__ gb,
    const float* __restrict__ eW,  const float* __restrict__ eb,
    const float* __restrict__ wq,  const float* __restrict__ wqb,
    const float* __restrict__ wk,  const float* __restrict__ wkb,
    const float* __restrict__ wv,  const float* __restrict__ wvb,
    const float* __restrict__ wo,  const float* __restrict__ wob,
    float* __restrict__ out)
{
    __shared__ __align__(16) float Xs[16][36];     // K-tile x 32 rows
    __shared__ __align__(16) float Ws[16][128];
    __shared__ __align__(16) float h_s[32][132];   // tanh(router) outputs
    __shared__ __align__(16) float hid_s[32][68];  // gate outputs (hidden)

    const int tid  = threadIdx.x;
    const int row0 = blockIdx.x * 32;
    const int cid  = tid & 31;   // col group: cols 4*cid..+3
    const int rid  = tid >> 5;   // row group: rows 4*rid..+3

    float acc[4][4];
#pragma unroll
    for (int i = 0; i < 4; ++i)
#pragma unroll
        for (int j = 0; j < 4; ++j) acc[i][j] = 0.f;

    // ---------------- GEMM1: h = X @ router_W -------------------------------
    for (int kb = 0; kb < XLD; kb += 16) {
        // load X tile (32 rows x 16 k), stored transposed Xs[k][r]
        {
            int r = tid >> 4, k = tid & 15;
            Xs[k][r]      = g_X[(size_t)(row0 + r) * XLD + kb + k];
            Xs[k][r + 16] = g_X[(size_t)(row0 + r + 16) * XLD + kb + k];
        }
        // load W tile (16 k x 128 cols) with X-col -> W-row remap
        {
            int gk = kb + rid;               // X column index
            float4 w0 = make_float4(0.f, 0.f, 0.f, 0.f);
            if (gk < 1182) {
                int wr = (gk < 1024) ? (gk + 158) : (gk - 1024);
                w0 = *(const float4*)(rW + (size_t)wr * 128 + cid * 4);
            }
            *(float4*)&Ws[rid][cid * 4] = w0;
            gk += 8;
            float4 w1 = make_float4(0.f, 0.f, 0.f, 0.f);
            if (gk < 1182) {
                int wr = (gk < 1024) ? (gk + 158) : (gk - 1024);
                w1 = *(const float4*)(rW + (size_t)wr * 128 + cid * 4);
            }
            *(float4*)&Ws[rid + 8][cid * 4] = w1;
        }
        __syncthreads();
#pragma unroll
        for (int k = 0; k < 16; ++k) {
            float4 xv = *(const float4*)&Xs[k][rid * 4];  // broadcast in warp
            float4 wv4 = *(const float4*)&Ws[k][cid * 4];
            acc[0][0] = fmaf(xv.x, wv4.x, acc[0][0]);
            acc[0][1] = fmaf(xv.x, wv4.y, acc[0][1]);
            acc[0][2] = fmaf(xv.x, wv4.z, acc[0][2]);
            acc[0][3] = fmaf(xv.x, wv4.w, acc[0][3]);
            acc[1][0] = fmaf(xv.y, wv4.x, acc[1][0]);
            acc[1][1] = fmaf(xv.y, wv4.y, acc[1][1]);
            acc[1][2] = fmaf(xv.y, wv4.z, acc[1][2]);
            acc[1][3] = fmaf(xv.y, wv4.w, acc[1][3]);
            acc[2][0] = fmaf(xv.z, wv4.x, acc[2][0]);
            acc[2][1] = fmaf(xv.z, wv4.y, acc[2][1]);
            acc[2][2] = fmaf(xv.z, wv4.z, acc[2][2]);
            acc[2][3] = fmaf(xv.z, wv4.w, acc[2][3]);
            acc[3][0] = fmaf(xv.w, wv4.x, acc[3][0]);
            acc[3][1] = fmaf(xv.w, wv4.y, acc[3][1]);
            acc[3][2] = fmaf(xv.w, wv4.z, acc[3][2]);
            acc[3][3] = fmaf(xv.w, wv4.w, acc[3][3]);
        }
        __syncthreads();
    }
    // tanh + store to h_s
#pragma unroll
    for (int rr = 0; rr < 4; ++rr)
#pragma unroll
        for (int cc = 0; cc < 4; ++cc) {
            int c = cid * 4 + cc;
            h_s[rid * 4 + rr][c] = tanhf(acc[rr][cc] + __ldg(rb + c));
        }
    __syncthreads();

    // ---------------- GEMM2: hidden = h @ gate_W (128x64) -------------------
    {
        int r2 = tid >> 3;           // 0..31
        int j0 = (tid & 7) * 8;      // 0,8,..,56
        float ha[8];
#pragma unroll
        for (int j = 0; j < 8; ++j) ha[j] = __ldg(gb + j0 + j);
#pragma unroll 8
        for (int k = 0; k < 128; ++k) {
            float hv = h_s[r2][k];
            float4 g0 = *(const float4*)(gW + (size_t)k * 64 + j0);
            float4 g1 = *(const float4*)(gW + (size_t)k * 64 + j0 + 4);
            ha[0] = fmaf(hv, g0.x, ha[0]);
            ha[1] = fmaf(hv, g0.y, ha[1]);
            ha[2] = fmaf(hv, g0.z, ha[2]);
            ha[3] = fmaf(hv, g0.w, ha[3]);
            ha[4] = fmaf(hv, g1.x, ha[4]);
            ha[5] = fmaf(hv, g1.y, ha[5]);
            ha[6] = fmaf(hv, g1.z, ha[6]);
            ha[7] = fmaf(hv, g1.w, ha[7]);
        }
        int n = row0 + r2;
        float* ho = out + OFF_HID + (size_t)n * 64 + j0;
#pragma unroll
        for (int j = 0; j < 8; ++j) {
            hid_s[r2][j0 + j] = ha[j];
            ho[j] = ha[j];
        }
    }
    __syncthreads();

    // ---------------- Epilogue: top2 + routing + sparse expert path ---------
    // 8-lane groups; group handles one row. warp w, group grp -> row w*4+grp.
    const int lane = tid & 31;
    const int warp = tid >> 5;
    const int L    = lane & 7;           // lane within group (e / f index)
    const int r    = warp * 4 + (lane >> 3);
    const int n    = row0 + r;

    // local top2 over indices L*8 .. L*8+7 (increasing index, strict > keeps
    // the earliest index like jax top_k)
    float v1 = -INFINITY, v2 = -INFINITY;
    int   i1 = 0, i2 = 0;
#pragma unroll
    for (int j = 0; j < 8; ++j) {
        int idx = L * 8 + j;
        float v = hid_s[r][idx];
        if (v > v1) { v2 = v1; i2 = i1; v1 = v; i1 = idx; }
        else if (v > v2) { v2 = v; i2 = idx; }
    }
    // segment reduce with ASCENDING deltas so the left operand always holds
    // the lower-index block (stable tie-breaking).
#pragma unroll
    for (int d = 1; d <= 4; d <<= 1) {
        float b1 = __shfl_down_sync(0xffffffffu, v1, d, 8);
        int  bi1 = __shfl_down_sync(0xffffffffu, i1, d, 8);
        float b2 = __shfl_down_sync(0xffffffffu, v2, d, 8);
        int  bi2 = __shfl_down_sync(0xffffffffu, i2, d, 8);
        if (b1 > v1) {
            if (v1 >= b2) { v2 = v1; i2 = i1; }
            else          { v2 = b2; i2 = bi2; }
            v1 = b1; i1 = bi1;
        } else if (b1 > v2) {
            v2 = b1; i2 = bi1;
        }
    }
    float rw1 = 0.f, rw2 = 0.f;
    if (L == 0) {
        float e2 = expf(v2 - v1);          // exactly mirrors masked softmax
        float inv = 1.f / (1.f + e2);      // (all other lanes give exp==0)
        rw1 = inv;
        rw2 = e2 * inv;
    }
    // broadcast winners to the 8-lane group
    i1  = __shfl_sync(0xffffffffu, i1, 0, 8);
    i2  = __shfl_sync(0xffffffffu, i2, 0, 8);
    rw1 = __shfl_sync(0xffffffffu, rw1, 0, 8);
    rw2 = __shfl_sync(0xffffffffu, rw2, 0, 8);

    // routing_weights (two copies) — sparse
#pragma unroll
    for (int j = 0; j < 8; ++j) {
        int idx = L * 8 + j;
        float val = (idx == i1) ? rw1 : ((idx == i2) ? rw2 : 0.f);
        out[OFF_RW1 + (size_t)n * 64 + idx] = val;
        out[OFF_RW2 + (size_t)n * 64 + idx] = val;
    }
    if (L == 0) {
        out[OFF_TK + (size_t)n * 2 + 0] = (float)i1;
        out[OFF_TK + (size_t)n * 2 + 1] = (float)i2;
    }

    // predictions: only the 2 selected experts matter (others have rw == 0)
    float pred = 0.f;
#pragma unroll
    for (int s = 0; s < 2; ++s) {
        int sel  = s ? i2 : i1;
        float rw = s ? rw2 : rw1;
        int g = sel >> 3, f = sel & 7;

        // expert_out[e=L] = hidden . expert_W[g][L] + eb
        float eo = __ldg(eb + g * 8 + L);
        const float* ew = eW + (size_t)(g * 8 + L) * 64;
#pragma unroll 16
        for (int h = 0; h < 64; ++h)
            eo = fmaf(hid_s[r][h], __ldg(ew + h), eo);

        // q,k,v for f = L (needs all 8 eo values -> shuffle)
        float qf = __ldg(wqb + g * 8 + L);
        float kf = __ldg(wkb + g * 8 + L);
        float vf = __ldg(wvb + g * 8 + L);
        const float* wqr = wq + (size_t)(g * 8 + L) * 8;
        const float* wkr = wk + (size_t)(g * 8 + L) * 8;
        const float* wvr = wv + (size_t)(g * 8 + L) * 8;
#pragma unroll
        for (int e = 0; e < 8; ++e) {
            float eoe = __shfl_sync(0xffffffffu, eo, e, 8);
            qf = fmaf(eoe, __ldg(wqr + e), qf);
            kf = fmaf(eoe, __ldg(wkr + e), kf);
            vf = fmaf(eoe, __ldg(wvr + e), vf);
        }
        // gather full q/k/v vectors to every lane (cheap, unrolled -> regs)
        float q8[8], k8[8], v8[8];
#pragma unroll
        for (int e = 0; e < 8; ++e) {
            q8[e] = __shfl_sync(0xffffffffu, qf, e, 8);
            k8[e] = __shfl_sync(0xffffffffu, kf, e, 8);
            v8[e] = __shfl_sync(0xffffffffu, vf, e, 8);
        }
        // scores[d][e] = sum_h q8[2h+d]*k8[2h+e] / sqrt(2)
        float s00 = 0.f, s01 = 0.f, s10 = 0.f, s11 = 0.f;
#pragma unroll
        for (int h = 0; h < 4; ++h) {
            float q0 = q8[2 * h], q1 = q8[2 * h + 1];
            float k0 = k8[2 * h], k1 = k8[2 * h + 1];
            s00 = fmaf(q0, k0, s00); s01 = fmaf(q0, k1, s01);
            s10 = fmaf(q1, k0, s10); s11 = fmaf(q1, k1, s11);
        }
        const float is2 = 0.70710678118654752440f;
        s00 *= is2; s01 *= is2; s10 *= is2; s11 *= is2;
        float m0 = fmaxf(s00, s01);
        float e00 = expf(s00 - m0), e01 = expf(s01 - m0);
        float n0 = 1.f / (e00 + e01);
        float a00 = e00 * n0, a01 = e01 * n0;
        float m1 = fmaxf(s10, s11);
        float e10 = expf(s10 - m1), e11 = expf(s11 - m1);
        float n1 = 1.f / (e10 + e11);
        float a10 = e10 * n1, a11 = e11 * n1;

        // attended -> att_vec[2h+d]
        float att[8];
#pragma unroll
        for (int h = 0; h < 4; ++h) {
            att[2 * h]     = fmaf(a00, v8[2 * h], a01 * v8[2 * h + 1]);
            att[2 * h + 1] = fmaf(a10, v8[2 * h], a11 * v8[2 * h + 1]);
        }
        // agg[f] = att . wo[g][f] + wob
        float aggf = __ldg(wob + g * 8 + f);
        const float* wor = wo + (size_t)(g * 8 + f) * 8;
#pragma unroll
        for (int e = 0; e < 8; ++e)
            aggf = fmaf(att[e], __ldg(wor + e), aggf);

        pred = fmaf(rw, aggf, pred);
    }
    if (L == 0) out[OFF_PRED + n] = pred;
}

// ---------------------------------------------------------------------------
extern "C" void kernel_launch(void* const* d_in, const int* in_sizes, int n_in,
                              void* d_out, int out_size)
{
    const float* price = (const float*)d_in[0];
    const float* news  = (const float*)d_in[1];
    const float* mask  = (const float*)d_in[2];
    const float* rW    = (const float*)d_in[3];
    const float* rb    = (const float*)d_in[4];
    const float* gW    = (const float*)d_in[5];
    const float* gb    = (const float*)d_in[6];
    const float* eW    = (const float*)d_in[7];
    const float* eb    = (const float*)d_in[8];
    const float* wq    = (const float*)d_in[9];
    const float* wqb   = (const float*)d_in[10];
    const float* wk    = (const float*)d_in[11];
    const float* wkb   = (const float*)d_in[12];
    const float* wv    = (const float*)d_in[13];
    const float* wvb   = (const float*)d_in[14];
    const float* wo    = (const float*)d_in[15];
    const float* wob   = (const float*)d_in[16];
    float* out = (float*)d_out;

    k_agg<<<NROWS, 256>>>(price, news, mask);
    k_main<<<NROWS / 32, 256>>>(rW, rb, gW, gb, eW, eb,
                                wq, wqb, wk, wkb, wv, wvb, wo, wob, out);
}

// round 5
// speedup vs baseline: 1.5465x; 1.5465x over previous
#include <cuda_runtime.h>
#include <math.h>

typedef unsigned long long ull;

// Shapes
#define NROWS 4096
#define XLD   1184   // padded 1182 -> 1184 (news[1024] | price[158] | 2 zeros)
#define NT    74     // 1184 / 16 k-tiles
#define OFF_PRED 0
#define OFF_RW1  (NROWS)
#define OFF_HID  (NROWS + NROWS*64)
#define OFF_TK   (NROWS + 2*NROWS*64)
#define OFF_RW2  (NROWS + 2*NROWS*64 + NROWS*2)

// Scratch: X = [news_agg(1024) | price_agg(158) | pad2], row-major, 4096 x 1184
__device__ float g_X[(size_t)NROWS * XLD];
// Scratch: remapped+padded router_W: g_W2[k][c], k in X-column order, 1184x128
__device__ float g_W2[(size_t)XLD * 128];

// ---------------------------------------------------------------------------
// f32x2 helpers (FFMA2 reachable only via PTX)
// ---------------------------------------------------------------------------
__device__ __forceinline__ ull pk2(float v) {
    ull r; asm("mov.b64 %0, {%1,%1};" : "=l"(r) : "f"(v)); return r;
}
__device__ __forceinline__ void fma2(ull& d, ull a, ull b) {
    asm("fma.rn.f32x2 %0, %1, %2, %0;" : "+l"(d) : "l"(a), "l"(b));
}
__device__ __forceinline__ void unpk2(ull v, float& lo, float& hi) {
    asm("mov.b64 {%0,%1}, %2;" : "=f"(lo), "=f"(hi) : "l"(v));
}
union F4U { float4 f; ull u[2]; };

// ---------------------------------------------------------------------------
// Kernel 0: remap router_W rows into X-column order, zero-pad to 1184 rows
// ---------------------------------------------------------------------------
__global__ __launch_bounds__(256) void k_prep(const float* __restrict__ rW)
{
    int idx = blockIdx.x * 256 + threadIdx.x;   // over 1184*128
    int k = idx >> 7, c = idx & 127;
    float v = 0.f;
    if (k < 1182) {
        int wr = (k < 1024) ? (k + 158) : (k - 1024);
        v = __ldg(rW + (size_t)wr * 128 + c);
    }
    g_W2[idx] = v;
}

// ---------------------------------------------------------------------------
// Kernel 1: masked news aggregation + price mean -> g_X   (memory-bound)
// ---------------------------------------------------------------------------
__global__ __launch_bounds__(256) void k_agg(const float* __restrict__ price,
                                             const float* __restrict__ news,
                                             const float* __restrict__ mask)
{
    int n   = blockIdx.x;
    int tid = threadIdx.x;
    const float* nf   = news  + (size_t)n * 32 * 1024 + tid * 4;
    const float* pf   = price + (size_t)n * 32 * 158;
    const float* mrow = mask  + n * 32;

    float4 acc = make_float4(0.f, 0.f, 0.f, 0.f);
    float msum = 0.f, pacc = 0.f;

#pragma unroll 4
    for (int t = 0; t < 32; ++t) {
        float m = __ldg(mrow + t);
        msum += m;
        float4 v = *(const float4*)(nf + t * 1024);
        acc.x = fmaf(m, v.x, acc.x);
        acc.y = fmaf(m, v.y, acc.y);
        acc.z = fmaf(m, v.z, acc.z);
        acc.w = fmaf(m, v.w, acc.w);
        if (tid < 158) pacc += __ldg(pf + t * 158 + tid);
    }

    float inv = 1.f / fmaxf(msum, 1e-6f);
    float* xr = g_X + (size_t)n * XLD;
    *(float4*)(xr + tid * 4) =
        make_float4(acc.x * inv, acc.y * inv, acc.z * inv, acc.w * inv);
    if (tid < 158)       xr[1024 + tid] = pacc * (1.f / 32.f);
    else if (tid < 160)  xr[1024 + tid] = 0.f;   // zero pad cols 1182,1183
}

// ---------------------------------------------------------------------------
// Kernel 2: fused router GEMM (FFMA2, double-buffered) + gate GEMM + top2
// routing + sparse expert path. 128 blocks x 256 threads, 32 rows/block.
// Warp tiling: warp = 8 rows x 64 cols; thread = 4 rows x 4 cols.
// ---------------------------------------------------------------------------
__global__ __launch_bounds__(256) void k_main(
    const float* __restrict__ rb,
    const float* __restrict__ gW,  const float* __restrict__ gb,
    const float* __restrict__ eW,  const float* __restrict__ eb,
    const float* __restrict__ wq,  const float* __restrict__ wqb,
    const float* __restrict__ wk,  const float* __restrict__ wkb,
    const float* __restrict__ wv,  const float* __restrict__ wvb,
    const float* __restrict__ wo,  const float* __restrict__ wob,
    float* __restrict__ out)
{
    __shared__ __align__(16) float Xs[2][16][36];   // [buf][k][row] (pad 36)
    __shared__ __align__(16) float Ws[2][16][128];  // [buf][k][col]
    __shared__ __align__(16) float h_s[32][132];    // tanh(router) outputs
    __shared__ __align__(16) float hid_s[32][68];   // gate outputs (hidden)

    const int tid  = threadIdx.x;
    const int row0 = blockIdx.x * 32;

    // GEMM1 compute mapping: warp covers 8 rows x 64 cols
    const int wid  = tid >> 5;
    const int lane = tid & 31;
    const int xoff = (wid & 3) * 8 + (lane >> 4) * 4;   // first of 4 rows
    const int woff = (wid >> 2) * 64 + (lane & 15) * 4; // first of 4 cols

    // GEMM1 loader mapping
    const int lr  = tid >> 3;          // 0..31  (X row)
    const int lk  = (tid & 7) * 2;     // 0..14  (X k within tile)
    const int wk1 = tid >> 5;          // 0..7   (W k within tile)
    const int wc4 = (tid & 31) * 4;    // 0..124 (W col)
    const float* xsrc = g_X + (size_t)(row0 + lr) * XLD + lk;

    ull acc[2][4];
#pragma unroll
    for (int p = 0; p < 2; ++p)
#pragma unroll
        for (int c = 0; c < 4; ++c) acc[p][c] = 0ull;

    // prefetch registers
    float2 xpre;
    float4 wpreA, wpreB;

    // ---- prologue: tile 0 loaded+stored, tile 1 loaded ----------------------
    xpre  = *(const float2*)(xsrc);
    wpreA = *(const float4*)(g_W2 + (size_t)wk1 * 128 + wc4);
    wpreB = *(const float4*)(g_W2 + (size_t)(wk1 + 8) * 128 + wc4);
    Xs[0][lk][lr] = xpre.x;  Xs[0][lk + 1][lr] = xpre.y;
    *(float4*)&Ws[0][wk1][wc4]     = wpreA;
    *(float4*)&Ws[0][wk1 + 8][wc4] = wpreB;
    xpre  = *(const float2*)(xsrc + 16);
    wpreA = *(const float4*)(g_W2 + (size_t)(16 + wk1) * 128 + wc4);
    wpreB = *(const float4*)(g_W2 + (size_t)(16 + wk1 + 8) * 128 + wc4);
    __syncthreads();

    // ---- main pipeline: 1 barrier / tile ------------------------------------
#pragma unroll 1
    for (int it = 0; it < NT; ++it) {
        const int cur = it & 1;
        if (it + 1 < NT) {               // store tile it+1 (regs from prefetch)
            Xs[1 - cur][lk][lr] = xpre.x;  Xs[1 - cur][lk + 1][lr] = xpre.y;
            *(float4*)&Ws[1 - cur][wk1][wc4]     = wpreA;
            *(float4*)&Ws[1 - cur][wk1 + 8][wc4] = wpreB;
        }
        if (it + 2 < NT) {               // issue loads for tile it+2
            int kb = (it + 2) * 16;
            xpre  = *(const float2*)(xsrc + kb);
            wpreA = *(const float4*)(g_W2 + (size_t)(kb + wk1) * 128 + wc4);
            wpreB = *(const float4*)(g_W2 + (size_t)(kb + wk1 + 8) * 128 + wc4);
        }
#pragma unroll
        for (int k = 0; k < 16; ++k) {
            F4U xu, wu;
            xu.f = *(const float4*)&Xs[cur][k][xoff];   // 4 rows (2 pairs)
            wu.f = *(const float4*)&Ws[cur][k][woff];   // 4 cols
            ull b0 = pk2(wu.f.x), b1 = pk2(wu.f.y);
            ull b2 = pk2(wu.f.z), b3 = pk2(wu.f.w);
            fma2(acc[0][0], xu.u[0], b0);
            fma2(acc[0][1], xu.u[0], b1);
            fma2(acc[0][2], xu.u[0], b2);
            fma2(acc[0][3], xu.u[0], b3);
            fma2(acc[1][0], xu.u[1], b0);
            fma2(acc[1][1], xu.u[1], b1);
            fma2(acc[1][2], xu.u[1], b2);
            fma2(acc[1][3], xu.u[1], b3);
        }
        __syncthreads();
    }

    // ---- bias + tanh -> h_s --------------------------------------------------
#pragma unroll
    for (int p = 0; p < 2; ++p)
#pragma unroll
        for (int c = 0; c < 4; ++c) {
            float lo, hi;
            unpk2(acc[p][c], lo, hi);
            float b = __ldg(rb + woff + c);
            h_s[xoff + 2 * p][woff + c]     = tanhf(lo + b);
            h_s[xoff + 2 * p + 1][woff + c] = tanhf(hi + b);
        }
    __syncthreads();

    // ---------------- GEMM2: hidden = h @ gate_W (128x64) -------------------
    {
        int r2 = tid >> 3;           // 0..31
        int j0 = (tid & 7) * 8;      // 0,8,..,56
        float ha[8];
#pragma unroll
        for (int j = 0; j < 8; ++j) ha[j] = __ldg(gb + j0 + j);
#pragma unroll 8
        for (int k = 0; k < 128; ++k) {
            float hv = h_s[r2][k];
            float4 g0 = *(const float4*)(gW + (size_t)k * 64 + j0);
            float4 g1 = *(const float4*)(gW + (size_t)k * 64 + j0 + 4);
            ha[0] = fmaf(hv, g0.x, ha[0]);
            ha[1] = fmaf(hv, g0.y, ha[1]);
            ha[2] = fmaf(hv, g0.z, ha[2]);
            ha[3] = fmaf(hv, g0.w, ha[3]);
            ha[4] = fmaf(hv, g1.x, ha[4]);
            ha[5] = fmaf(hv, g1.y, ha[5]);
            ha[6] = fmaf(hv, g1.z, ha[6]);
            ha[7] = fmaf(hv, g1.w, ha[7]);
        }
        int n = row0 + r2;
        float* ho = out + OFF_HID + (size_t)n * 64 + j0;
#pragma unroll
        for (int j = 0; j < 8; ++j) {
            hid_s[r2][j0 + j] = ha[j];
            ho[j] = ha[j];
        }
    }
    __syncthreads();

    // ---------------- Epilogue: top2 + routing + sparse expert path ---------
    const int L = lane & 7;              // lane within 8-lane group
    const int r = wid * 4 + (lane >> 3); // local row
    const int n = row0 + r;

    float v1 = -INFINITY, v2 = -INFINITY;
    int   i1 = 0, i2 = 0;
#pragma unroll
    for (int j = 0; j < 8; ++j) {
        int idx = L * 8 + j;
        float v = hid_s[r][idx];
        if (v > v1) { v2 = v1; i2 = i1; v1 = v; i1 = idx; }
        else if (v > v2) { v2 = v; i2 = idx; }
    }
#pragma unroll
    for (int d = 1; d <= 4; d <<= 1) {
        float b1 = __shfl_down_sync(0xffffffffu, v1, d, 8);
        int  bi1 = __shfl_down_sync(0xffffffffu, i1, d, 8);
        float b2 = __shfl_down_sync(0xffffffffu, v2, d, 8);
        int  bi2 = __shfl_down_sync(0xffffffffu, i2, d, 8);
        if (b1 > v1) {
            if (v1 >= b2) { v2 = v1; i2 = i1; }
            else          { v2 = b2; i2 = bi2; }
            v1 = b1; i1 = bi1;
        } else if (b1 > v2) {
            v2 = b1; i2 = bi1;
        }
    }
    float rw1 = 0.f, rw2 = 0.f;
    if (L == 0) {
        float e2 = expf(v2 - v1);
        float inv = 1.f / (1.f + e2);
        rw1 = inv;
        rw2 = e2 * inv;
    }
    i1  = __shfl_sync(0xffffffffu, i1, 0, 8);
    i2  = __shfl_sync(0xffffffffu, i2, 0, 8);
    rw1 = __shfl_sync(0xffffffffu, rw1, 0, 8);
    rw2 = __shfl_sync(0xffffffffu, rw2, 0, 8);

#pragma unroll
    for (int j = 0; j < 8; ++j) {
        int idx = L * 8 + j;
        float val = (idx == i1) ? rw1 : ((idx == i2) ? rw2 : 0.f);
        out[OFF_RW1 + (size_t)n * 64 + idx] = val;
        out[OFF_RW2 + (size_t)n * 64 + idx] = val;
    }
    if (L == 0) {
        out[OFF_TK + (size_t)n * 2 + 0] = (float)i1;
        out[OFF_TK + (size_t)n * 2 + 1] = (float)i2;
    }

    float pred = 0.f;
#pragma unroll
    for (int s = 0; s < 2; ++s) {
        int sel  = s ? i2 : i1;
        float rw = s ? rw2 : rw1;
        int g = sel >> 3, f = sel & 7;

        float eo = __ldg(eb + g * 8 + L);
        const float* ew = eW + (size_t)(g * 8 + L) * 64;
#pragma unroll 16
        for (int h = 0; h < 64; ++h)
            eo = fmaf(hid_s[r][h], __ldg(ew + h), eo);

        float qf = __ldg(wqb + g * 8 + L);
        float kf = __ldg(wkb + g * 8 + L);
        float vf = __ldg(wvb + g * 8 + L);
        const float* wqr = wq + (size_t)(g * 8 + L) * 8;
        const float* wkr = wk + (size_t)(g * 8 + L) * 8;
        const float* wvr = wv + (size_t)(g * 8 + L) * 8;
#pragma unroll
        for (int e = 0; e < 8; ++e) {
            float eoe = __shfl_sync(0xffffffffu, eo, e, 8);
            qf = fmaf(eoe, __ldg(wqr + e), qf);
            kf = fmaf(eoe, __ldg(wkr + e), kf);
            vf = fmaf(eoe, __ldg(wvr + e), vf);
        }
        float q8[8], k8[8], v8[8];
#pragma unroll
        for (int e = 0; e < 8; ++e) {
            q8[e] = __shfl_sync(0xffffffffu, qf, e, 8);
            k8[e] = __shfl_sync(0xffffffffu, kf, e, 8);
            v8[e] = __shfl_sync(0xffffffffu, vf, e, 8);
        }
        float s00 = 0.f, s01 = 0.f, s10 = 0.f, s11 = 0.f;
#pragma unroll
        for (int h = 0; h < 4; ++h) {
            float q0 = q8[2 * h], q1 = q8[2 * h + 1];
            float k0 = k8[2 * h], k1 = k8[2 * h + 1];
            s00 = fmaf(q0, k0, s00); s01 = fmaf(q0, k1, s01);
            s10 = fmaf(q1, k0, s10); s11 = fmaf(q1, k1, s11);
        }
        const float is2 = 0.70710678118654752440f;
        s00 *= is2; s01 *= is2; s10 *= is2; s11 *= is2;
        float m0 = fmaxf(s00, s01);
        float e00 = expf(s00 - m0), e01 = expf(s01 - m0);
        float n0 = 1.f / (e00 + e01);
        float a00 = e00 * n0, a01 = e01 * n0;
        float m1 = fmaxf(s10, s11);
        float e10 = expf(s10 - m1), e11 = expf(s11 - m1);
        float n1 = 1.f / (e10 + e11);
        float a10 = e10 * n1, a11 = e11 * n1;

        float att[8];
#pragma unroll
        for (int h = 0; h < 4; ++h) {
            att[2 * h]     = fmaf(a00, v8[2 * h], a01 * v8[2 * h + 1]);
            att[2 * h + 1] = fmaf(a10, v8[2 * h], a11 * v8[2 * h + 1]);
        }
        float aggf = __ldg(wob + g * 8 + f);
        const float* wor = wo + (size_t)(g * 8 + f) * 8;
#pragma unroll
        for (int e = 0; e < 8; ++e)
            aggf = fmaf(att[e], __ldg(wor + e), aggf);

        pred = fmaf(rw, aggf, pred);
    }
    if (L == 0) out[OFF_PRED + n] = pred;
}

// ---------------------------------------------------------------------------
extern "C" void kernel_launch(void* const* d_in, const int* in_sizes, int n_in,
                              void* d_out, int out_size)
{
    const float* price = (const float*)d_in[0];
    const float* news  = (const float*)d_in[1];
    const float* mask  = (const float*)d_in[2];
    const float* rW    = (const float*)d_in[3];
    const float* rb    = (const float*)d_in[4];
    const float* gW    = (const float*)d_in[5];
    const float* gb    = (const float*)d_in[6];
    const float* eW    = (const float*)d_in[7];
    const float* eb    = (const float*)d_in[8];
    const float* wq    = (const float*)d_in[9];
    const float* wqb   = (const float*)d_in[10];
    const float* wk    = (const float*)d_in[11];
    const float* wkb   = (const float*)d_in[12];
    const float* wv    = (const float*)d_in[13];
    const float* wvb   = (const float*)d_in[14];
    const float* wo    = (const float*)d_in[15];
    const float* wob   = (const float*)d_in[16];
    float* out = (float*)d_out;

    k_prep<<<(XLD * 128) / 256, 256>>>(rW);
    k_agg<<<NROWS, 256>>>(price, news, mask);
    k_main<<<NROWS / 32, 256>>>(rb, gW, gb, eW, eb,
                                wq, wqb, wk, wkb, wv, wvb, wo, wob, out);
}